// round 8
// baseline (speedup 1.0000x reference)
#include <cuda_runtime.h>

// Loss_Antonymy: out = sum_i relu(1 + sign_i * tanh(||A1_i - S2_i||_2)),
// sign_i = -1 if labels[i]==2 else +1.
// N = 1048576, D = 64. Inputs: S2_out [N*64] f32, A1_out [N*64] f32, labels [N] int32.
// Output: 1 float.
//
// R8: R7 kernel unchanged (unroll x2, regs<=32, fused last-block finalize,
// single launch). Grid now matches the ACTUAL SM count (GB300 = 152, not 148):
// blocks = SMs * 8 -> one perfectly balanced wave, no 7-vs-8-block stragglers.

#define D 64

__device__ float        g_partial = 0.0f;
__device__ unsigned int g_count   = 0u;

__global__ __launch_bounds__(256, 8)
void loss_antonymy_kernel(const float* __restrict__ S2,
                          const float* __restrict__ A1,
                          const int* __restrict__ labels,
                          float* __restrict__ out,
                          int nrows)
{
    const int lane  = threadIdx.x & 31;
    const int half  = lane >> 4;        // 0 or 1: which row within a pair
    const int sub   = lane & 15;        // 16 float4 = 64 floats of one row
    const int gwarp = (blockIdx.x * blockDim.x + threadIdx.x) >> 5;
    const int nwarp = (gridDim.x * blockDim.x) >> 5;
    const int nquads = nrows >> 2;      // 4 rows per warp iteration

    float acc = 0.0f;

    for (int quad = gwarp; quad < nquads; quad += nwarp) {
        const long long row0 = (long long)quad * 4 + half;
        const long long row1 = row0 + 2;

        const float4* a0 = reinterpret_cast<const float4*>(A1 + row0 * D);
        const float4* s0 = reinterpret_cast<const float4*>(S2 + row0 * D);
        const float4* a1 = reinterpret_cast<const float4*>(A1 + row1 * D);
        const float4* s1 = reinterpret_cast<const float4*>(S2 + row1 * D);

        // front-batch 4 independent 16B loads (MLP=4 per thread)
        float4 av0 = __ldg(&a0[sub]);
        float4 sv0 = __ldg(&s0[sub]);
        float4 av1 = __ldg(&a1[sub]);
        float4 sv1 = __ldg(&s1[sub]);

        float dx0 = av0.x - sv0.x, dy0 = av0.y - sv0.y;
        float dz0 = av0.z - sv0.z, dw0 = av0.w - sv0.w;
        float ss0 = dx0*dx0 + dy0*dy0 + dz0*dz0 + dw0*dw0;

        float dx1 = av1.x - sv1.x, dy1 = av1.y - sv1.y;
        float dz1 = av1.z - sv1.z, dw1 = av1.w - sv1.w;
        float ss1 = dx1*dx1 + dy1*dy1 + dz1*dz1 + dw1*dw1;

        // reduce each across the 16 lanes of this half-warp
        #pragma unroll
        for (int o = 8; o > 0; o >>= 1) {
            ss0 += __shfl_xor_sync(0xffffffffu, ss0, o);
            ss1 += __shfl_xor_sync(0xffffffffu, ss1, o);
        }

        if (sub == 0) {
            float sign0 = (labels[row0] == 2) ? -1.0f : 1.0f;
            float sign1 = (labels[row1] == 2) ? -1.0f : 1.0f;
            acc += fmaxf(0.0f, fmaf(sign0, tanhf(sqrtf(ss0)), 1.0f));
            acc += fmaxf(0.0f, fmaf(sign1, tanhf(sqrtf(ss1)), 1.0f));
        }
    }

    // block reduction: intra-warp, then across warps via shared
    #pragma unroll
    for (int o = 16; o > 0; o >>= 1)
        acc += __shfl_xor_sync(0xffffffffu, acc, o);

    __shared__ float wsum[8];   // 256 threads -> 8 warps
    const int wid = threadIdx.x >> 5;
    if (lane == 0) wsum[wid] = acc;
    __syncthreads();

    if (wid == 0) {
        float v = (lane < (blockDim.x >> 5)) ? wsum[lane] : 0.0f;
        #pragma unroll
        for (int o = 4; o > 0; o >>= 1)
            v += __shfl_xor_sync(0xffffffffu, v, o);

        if (lane == 0) {
            // accumulate into device-global partial; last block finalizes
            atomicAdd(&g_partial, v);
            __threadfence();
            unsigned int ticket = atomicAdd(&g_count, 1u);
            if (ticket == gridDim.x - 1u) {
                // all blocks' adds are globally visible (each fenced before its
                // ticket). Read-and-reset so the next graph replay starts clean.
                float total = atomicExch(&g_partial, 0.0f);
                out[0] = total;
                atomicExch(&g_count, 0u);
            }
        }
    }
}

extern "C" void kernel_launch(void* const* d_in, const int* in_sizes, int n_in,
                              void* d_out, int out_size)
{
    const float* S2     = (const float*)d_in[0];
    const float* A1     = (const float*)d_in[1];
    const int*   labels = (const int*)d_in[2];
    float*       out    = (float*)d_out;

    const int nrows = in_sizes[2];   // labels element count = N

    // Match grid to the real SM count (GB300=152, B300-SXM=148) for one
    // perfectly balanced wave at 8 blocks/SM. Host-side query is capture-safe
    // (executes at capture time; graph records the resulting grid).
    static int sms = 0;
    if (sms == 0) {
        cudaDeviceGetAttribute(&sms, cudaDevAttrMultiProcessorCount, 0);
        if (sms <= 0) sms = 148;
    }
    const int blocks = sms * 8;

    loss_antonymy_kernel<<<blocks, 256>>>(S2, A1, labels, out, nrows);
}

// round 9
// speedup vs baseline: 1.0012x; 1.0012x over previous
#include <cuda_runtime.h>

// Loss_Antonymy: out = sum_i relu(1 + sign_i * tanh(||A1_i - S2_i||_2)),
// sign_i = -1 if labels[i]==2 else +1.
// N = 1048576, D = 64. Inputs: S2_out [N*64] f32, A1_out [N*64] f32, labels [N] int32.
// Output: 1 float.
//
// R9: identical to R8 except the float4 loads use evict-first streaming policy
// (__ldcs). R6 tested this WITHOUT the launch-bounds pin and regressed purely
// from regs 40 -> 6 blocks/SM -> two waves; here __launch_bounds__(256,8)
// holds regs at 32 so the cache-policy bit is the only delta.

#define D 64

__device__ float        g_partial = 0.0f;
__device__ unsigned int g_count   = 0u;

__global__ __launch_bounds__(256, 8)
void loss_antonymy_kernel(const float* __restrict__ S2,
                          const float* __restrict__ A1,
                          const int* __restrict__ labels,
                          float* __restrict__ out,
                          int nrows)
{
    const int lane  = threadIdx.x & 31;
    const int half  = lane >> 4;        // 0 or 1: which row within a pair
    const int sub   = lane & 15;        // 16 float4 = 64 floats of one row
    const int gwarp = (blockIdx.x * blockDim.x + threadIdx.x) >> 5;
    const int nwarp = (gridDim.x * blockDim.x) >> 5;
    const int nquads = nrows >> 2;      // 4 rows per warp iteration

    float acc = 0.0f;

    for (int quad = gwarp; quad < nquads; quad += nwarp) {
        const long long row0 = (long long)quad * 4 + half;
        const long long row1 = row0 + 2;

        const float4* a0 = reinterpret_cast<const float4*>(A1 + row0 * D);
        const float4* s0 = reinterpret_cast<const float4*>(S2 + row0 * D);
        const float4* a1 = reinterpret_cast<const float4*>(A1 + row1 * D);
        const float4* s1 = reinterpret_cast<const float4*>(S2 + row1 * D);

        // front-batch 4 independent 16B streaming loads (evict-first, no reuse)
        float4 av0 = __ldcs(&a0[sub]);
        float4 sv0 = __ldcs(&s0[sub]);
        float4 av1 = __ldcs(&a1[sub]);
        float4 sv1 = __ldcs(&s1[sub]);

        float dx0 = av0.x - sv0.x, dy0 = av0.y - sv0.y;
        float dz0 = av0.z - sv0.z, dw0 = av0.w - sv0.w;
        float ss0 = dx0*dx0 + dy0*dy0 + dz0*dz0 + dw0*dw0;

        float dx1 = av1.x - sv1.x, dy1 = av1.y - sv1.y;
        float dz1 = av1.z - sv1.z, dw1 = av1.w - sv1.w;
        float ss1 = dx1*dx1 + dy1*dy1 + dz1*dz1 + dw1*dw1;

        // reduce each across the 16 lanes of this half-warp
        #pragma unroll
        for (int o = 8; o > 0; o >>= 1) {
            ss0 += __shfl_xor_sync(0xffffffffu, ss0, o);
            ss1 += __shfl_xor_sync(0xffffffffu, ss1, o);
        }

        if (sub == 0) {
            float sign0 = (labels[row0] == 2) ? -1.0f : 1.0f;
            float sign1 = (labels[row1] == 2) ? -1.0f : 1.0f;
            acc += fmaxf(0.0f, fmaf(sign0, tanhf(sqrtf(ss0)), 1.0f));
            acc += fmaxf(0.0f, fmaf(sign1, tanhf(sqrtf(ss1)), 1.0f));
        }
    }

    // block reduction: intra-warp, then across warps via shared
    #pragma unroll
    for (int o = 16; o > 0; o >>= 1)
        acc += __shfl_xor_sync(0xffffffffu, acc, o);

    __shared__ float wsum[8];   // 256 threads -> 8 warps
    const int wid = threadIdx.x >> 5;
    if (lane == 0) wsum[wid] = acc;
    __syncthreads();

    if (wid == 0) {
        float v = (lane < (blockDim.x >> 5)) ? wsum[lane] : 0.0f;
        #pragma unroll
        for (int o = 4; o > 0; o >>= 1)
            v += __shfl_xor_sync(0xffffffffu, v, o);

        if (lane == 0) {
            // accumulate into device-global partial; last block finalizes
            atomicAdd(&g_partial, v);
            __threadfence();
            unsigned int ticket = atomicAdd(&g_count, 1u);
            if (ticket == gridDim.x - 1u) {
                // all blocks' adds are globally visible (each fenced before its
                // ticket). Read-and-reset so the next graph replay starts clean.
                float total = atomicExch(&g_partial, 0.0f);
                out[0] = total;
                atomicExch(&g_count, 0u);
            }
        }
    }
}

extern "C" void kernel_launch(void* const* d_in, const int* in_sizes, int n_in,
                              void* d_out, int out_size)
{
    const float* S2     = (const float*)d_in[0];
    const float* A1     = (const float*)d_in[1];
    const int*   labels = (const int*)d_in[2];
    float*       out    = (float*)d_out;

    const int nrows = in_sizes[2];   // labels element count = N

    // One perfectly balanced wave at 8 blocks/SM on the real SM count.
    static int sms = 0;
    if (sms == 0) {
        cudaDeviceGetAttribute(&sms, cudaDevAttrMultiProcessorCount, 0);
        if (sms <= 0) sms = 148;
    }
    const int blocks = sms * 8;

    loss_antonymy_kernel<<<blocks, 256>>>(S2, A1, labels, out, nrows);
}